// round 11
// baseline (speedup 1.0000x reference)
#include <cuda_runtime.h>
#include <cstdint>

// ---------------------------------------------------------------------------
// RejectionSampler: chain speculative sampling, flashinfer-style.
// JAX threefry2x32 PARTITIONABLE streams (bit-exact, verified rel_err=0.0):
//   split(key,3):  key_i = threefry2x32(key, 0, i)
//   random_bits32: bits_j = o0 ^ o1 of threefry2x32(key, 0, j)
// argmax(log(x+EPS)+gumbel) computed as argmax x / (-log2 u)  (monotone).
// R11: R10's balanced pipe mix (mul.wide rotates, division-free compare,
//      lg2 domain) + ILP=2 in the drain loop: two independent threefry
//      chains per thread hide the mul.wide chain latency that collapsed
//      issue to 64% in R10.
// Output FLOAT32: [ (B,N+1) tokens | (B,) accepted | (B,) emitted ]
// ---------------------------------------------------------------------------

#define B_  64
#define N_  8
#define V_  128000
#define ROWS (B_ * N_)              // 512
#define SPLITS_R 25
#define SPLITS_B 16
#define THREADS_R 256
#define WARPS_R (THREADS_R / 32)    // 8
#define CHUNK_R (V_ / SPLITS_R)     // 5120 elements per block
#define WCHUNK4 ((CHUNK_R / WARPS_R) / 4) // 160 float4 per warp
#define WITERS  (WCHUNK4 / 32)      // 5 exact iterations
#define GRID_REC (ROWS * SPLITS_R)  // 12800
#define GRID_BON (B_ * SPLITS_B)    // 1024
#define GRID_TOT (GRID_REC + GRID_BON)
#define CAP 128                     // per-warp per-iteration buffer
#define TINY_F 1.17549435e-38f

// scratch (no allocations allowed)
__device__ float g_rval[ROWS * SPLITS_R];
__device__ int   g_ridx[ROWS * SPLITS_R];
__device__ float g_bval[B_ * SPLITS_B];
__device__ int   g_bidx[B_ * SPLITS_B];
__device__ unsigned g_done = 0;

// runtime-opaque rotation multipliers (2^r); ptxas can't fold them
struct Rot {
    uint32_t m13, m15, m26, m6, m17, m29, m16, m24;
};

// rotl(v,r) = lo|hi of (u64)v * 2^r ; mul.wide.u32 lands on the fma pipe
__device__ __forceinline__ uint32_t rot_mul(uint32_t v, uint32_t m) {
    unsigned long long w;
    asm("mul.wide.u32 %0, %1, %2;" : "=l"(w) : "r"(v), "r"(m));
    return (uint32_t)w | (uint32_t)(w >> 32);
}

// ---------------- threefry2x32 (JAX-compatible) ----------------
__device__ __forceinline__ void threefry2x32_dev(
    uint32_t k0, uint32_t k1, uint32_t x0, uint32_t x1,
    const Rot& rm, uint32_t* y0, uint32_t* y1)
{
    uint32_t k2 = k0 ^ k1 ^ 0x1BD11BDAu;
    x0 += k0; x1 += k1;
#define TF_RND(m) { x0 += x1; x1 = rot_mul(x1, rm.m) ^ x0; }
    TF_RND(m13) TF_RND(m15) TF_RND(m26) TF_RND(m6)   x0 += k1; x1 += k2 + 1u;
    TF_RND(m17) TF_RND(m29) TF_RND(m16) TF_RND(m24)  x0 += k2; x1 += k0 + 2u;
    TF_RND(m13) TF_RND(m15) TF_RND(m26) TF_RND(m6)   x0 += k0; x1 += k1 + 3u;
    TF_RND(m17) TF_RND(m29) TF_RND(m16) TF_RND(m24)  x0 += k1; x1 += k2 + 4u;
    TF_RND(m13) TF_RND(m15) TF_RND(m26) TF_RND(m6)   x0 += k2; x1 += k0 + 5u;
#undef TF_RND
    *y0 = x0; *y1 = x1;
}

// TWO independent threefry chains, interleaved by the scheduler (ILP=2)
__device__ __forceinline__ void tf_bits32_x2(
    uint32_t k0, uint32_t k1, uint32_t ja, uint32_t jb,
    const Rot& rm, uint32_t* ba, uint32_t* bb)
{
    uint32_t k2 = k0 ^ k1 ^ 0x1BD11BDAu;
    uint32_t a0 = k0, a1 = ja + k1;
    uint32_t b0 = k0, b1 = jb + k1;
#define TF_RND2(m) { \
    a0 += a1; a1 = rot_mul(a1, rm.m) ^ a0; \
    b0 += b1; b1 = rot_mul(b1, rm.m) ^ b0; }
    TF_RND2(m13) TF_RND2(m15) TF_RND2(m26) TF_RND2(m6)
    a0 += k1; a1 += k2 + 1u;  b0 += k1; b1 += k2 + 1u;
    TF_RND2(m17) TF_RND2(m29) TF_RND2(m16) TF_RND2(m24)
    a0 += k2; a1 += k0 + 2u;  b0 += k2; b1 += k0 + 2u;
    TF_RND2(m13) TF_RND2(m15) TF_RND2(m26) TF_RND2(m6)
    a0 += k0; a1 += k1 + 3u;  b0 += k0; b1 += k1 + 3u;
    TF_RND2(m17) TF_RND2(m29) TF_RND2(m16) TF_RND2(m24)
    a0 += k1; a1 += k2 + 4u;  b0 += k1; b1 += k2 + 4u;
    TF_RND2(m13) TF_RND2(m15) TF_RND2(m26) TF_RND2(m6)
    a0 += k2; a1 += k0 + 5u;  b0 += k2; b1 += k0 + 5u;
#undef TF_RND2
    *ba = a0 ^ a1;
    *bb = b0 ^ b1;
}

// host copy (plain shifts)
inline void threefry2x32_host(
    uint32_t k0, uint32_t k1, uint32_t x0, uint32_t x1,
    uint32_t* y0, uint32_t* y1)
{
    uint32_t k2 = k0 ^ k1 ^ 0x1BD11BDAu;
    x0 += k0; x1 += k1;
#define ROTL32(v, r) (((v) << (r)) | ((v) >> (32 - (r))))
#define TF_RND(r) { x0 += x1; x1 = ROTL32(x1, r); x1 ^= x0; }
    TF_RND(13) TF_RND(15) TF_RND(26) TF_RND(6)   x0 += k1; x1 += k2 + 1u;
    TF_RND(17) TF_RND(29) TF_RND(16) TF_RND(24)  x0 += k2; x1 += k0 + 2u;
    TF_RND(13) TF_RND(15) TF_RND(26) TF_RND(6)   x0 += k0; x1 += k1 + 3u;
    TF_RND(17) TF_RND(29) TF_RND(16) TF_RND(24)  x0 += k1; x1 += k2 + 4u;
    TF_RND(13) TF_RND(15) TF_RND(26) TF_RND(6)   x0 += k2; x1 += k0 + 5u;
#undef TF_RND
#undef ROTL32
    *y0 = x0; *y1 = x1;
}

__device__ __forceinline__ uint32_t tf_bits32(uint32_t k0, uint32_t k1,
                                              uint32_t j, const Rot& rm) {
    uint32_t o0, o1;
    threefry2x32_dev(k0, k1, 0u, j, rm, &o0, &o1);
    return o0 ^ o1;
}

// bits -> uniform [0,1) exactly as JAX
__device__ __forceinline__ float bits_to_u(uint32_t bits) {
    return __uint_as_float((bits >> 9) | 0x3f800000u) - 1.0f;
}
// bits -> L = -log2(u') with u' = (u==0 ? tiny : u)
__device__ __forceinline__ float bits_to_L(uint32_t bits) {
    float u = bits_to_u(bits);
    if (u == 0.0f) u = TINY_F;
    return -__log2f(u);
}

// warp-wide argmax butterfly (max value, min index on tie)
__device__ __forceinline__ void warp_argmax(float& bv, int& bi) {
#pragma unroll
    for (int o = 16; o > 0; o >>= 1) {
        float v2 = __shfl_xor_sync(0xFFFFFFFFu, bv, o);
        int   i2 = __shfl_xor_sync(0xFFFFFFFFu, bi, o);
        if (v2 > bv || (v2 == bv && i2 < bi)) { bv = v2; bi = i2; }
    }
}

// ---------------- fused kernel ----------------
__global__ __launch_bounds__(THREADS_R)
void fused_kernel(const float* __restrict__ verify,
                  const float* __restrict__ draft,
                  const int* __restrict__ ids,
                  float* __restrict__ out,
                  uint32_t ku0, uint32_t ku1,
                  uint32_t kr0, uint32_t kr1,
                  uint32_t kb0, uint32_t kb1,
                  uint32_t one)
{
    __shared__ uint2 ebuf[WARPS_R][CAP];    // packed (value bits, index)
    __shared__ float swv[WARPS_R];
    __shared__ int   swi[WARPS_R];
    __shared__ float f_su[ROWS];
    __shared__ int   f_rec[ROWS];
    __shared__ int   f_bon[B_];
    __shared__ unsigned s_rank;

    // rotation multipliers from opaque 'one' (=1): runtime values, no folding
    Rot rm;
    rm.m13 = one << 13; rm.m15 = one << 15; rm.m26 = one << 26; rm.m6  = one << 6;
    rm.m17 = one << 17; rm.m29 = one << 29; rm.m16 = one << 16; rm.m24 = one << 24;

    const int t    = threadIdx.x;
    const int lane = t & 31;
    const int warp = t >> 5;

    float bv = -1.0f;
    int   bi = 0;

    if (blockIdx.x < GRID_REC) {
        // ---- recovered: compaction, drain each iteration with ILP=2 ----
        const int row = blockIdx.x / SPLITS_R;      // 0..511
        const int s   = blockIdx.x % SPLITS_R;
        const long vOff = ((long)(row >> 3) * 9 + (row & 7)) * V_;
        const long dOff = (long)row * V_;
        const int v0 = s * CHUNK_R;

        const float4* vr4 = (const float4*)(verify + vOff + v0);
        const float4* dr4 = (const float4*)(draft  + dOff + v0);

        const int qbase = warp * WCHUNK4;
        const uint32_t rowbase = (uint32_t)row * (uint32_t)V_;
        bi = v0;

#pragma unroll
        for (int it = 0; it < WITERS; it++) {
            int q = qbase + it * 32 + lane;         // always in range
            float4 va = vr4[q], da = dr4[q];
            float r[4] = { va.x - da.x, va.y - da.y, va.z - da.z, va.w - da.w };
            int ebase = v0 + q * 4;
            int cnt = 0;                             // warp-uniform
#pragma unroll
            for (int j = 0; j < 4; j++) {
                bool pos = r[j] > 0.0f;
                unsigned m = __ballot_sync(0xFFFFFFFFu, pos);
                if (pos) {
                    int slot = cnt + __popc(m & ((1u << lane) - 1u));
                    ebuf[warp][slot] = make_uint2(__float_as_uint(r[j]),
                                                  (uint32_t)(ebase + j));
                }
                cnt += __popc(m);
            }
            __syncwarp();
            // drain: two independent threefry chains per iteration (ILP=2)
            for (int k = lane; k < cnt; k += 64) {
                int k2 = k + 32;
                bool has2 = k2 < cnt;
                uint2 e1 = ebuf[warp][k];
                uint2 e2 = ebuf[warp][has2 ? k2 : k];
                uint32_t b1, b2;
                tf_bits32_x2(kr0, kr1, rowbase + e1.y, rowbase + e2.y,
                             rm, &b1, &b2);
                float L1 = bits_to_L(b1);
                float L2 = bits_to_L(b2);
                float r1 = __uint_as_float(e1.x);
                float r2 = __uint_as_float(e2.x);
                if (r1 > bv * L1) { bv = __fdividef(r1, L1); bi = (int)e1.y; }
                if (has2 && r2 > bv * L2) { bv = __fdividef(r2, L2); bi = (int)e2.y; }
            }
            __syncwarp();
        }

        warp_argmax(bv, bi);
        if (lane == 0) { swv[warp] = bv; swi[warp] = bi; }
        __syncthreads();
        if (warp == 0) {
            float v = (lane < WARPS_R) ? swv[lane] : -2.0f;
            int   i = (lane < WARPS_R) ? swi[lane] : 0x7FFFFFFF;
            warp_argmax(v, i);
            if (lane == 0) {
                g_rval[row * SPLITS_R + s] = v;
                g_ridx[row * SPLITS_R + s] = i;
            }
        }
    } else {
        // ---- bonus: all elements need RNG (ILP=4 via j-unroll) ----
        const int bid = blockIdx.x - GRID_REC;
        const int b = bid / SPLITS_B;               // 0..63
        const int s = bid % SPLITS_B;
        const long vOff = ((long)b * 9 + 8) * V_;

        const int chunk = V_ / SPLITS_B;            // 8000
        const int v0 = s * chunk;
        const float4* p4 = (const float4*)(verify + vOff + v0);
        bi = v0;

        const int n4 = chunk / 4;                   // 2000
        for (int q = t; q < n4; q += THREADS_R) {
            float4 pa = p4[q];
            int vbase = v0 + q * 4;
            uint32_t cbase = (uint32_t)b * (uint32_t)V_ + (uint32_t)vbase;
            float f[4] = { pa.x, pa.y, pa.z, pa.w };
            uint32_t bb[4];
            tf_bits32_x2(kb0, kb1, cbase + 0, cbase + 1, rm, &bb[0], &bb[1]);
            tf_bits32_x2(kb0, kb1, cbase + 2, cbase + 3, rm, &bb[2], &bb[3]);
#pragma unroll
            for (int j = 0; j < 4; j++) {
                float L = bits_to_L(bb[j]);
                if (f[j] > bv * L) {
                    bv = __fdividef(f[j], L);
                    bi = vbase + j;
                }
            }
        }

        warp_argmax(bv, bi);
        if (lane == 0) { swv[warp] = bv; swi[warp] = bi; }
        __syncthreads();
        if (warp == 0) {
            float v = (lane < WARPS_R) ? swv[lane] : -2.0f;
            int   i = (lane < WARPS_R) ? swi[lane] : 0x7FFFFFFF;
            warp_argmax(v, i);
            if (lane == 0) {
                g_bval[b * SPLITS_B + s] = v;
                g_bidx[b * SPLITS_B + s] = i;
            }
        }
    }

    // ---- last-block finalize ----
    __threadfence();
    if (t == 0) s_rank = atomicAdd(&g_done, 1u);
    __syncthreads();
    if (s_rank != GRID_TOT - 1) return;

    for (int i = t; i < ROWS; i += THREADS_R)
        f_su[i] = bits_to_u(tf_bits32(ku0, ku1, (uint32_t)i, rm));

    for (int row = t; row < ROWS; row += THREADS_R) {
        float mv = -2.0f; int mi = 0;
        for (int s = 0; s < SPLITS_R; s++) {
            float v = g_rval[row * SPLITS_R + s];
            int   i = g_ridx[row * SPLITS_R + s];
            if (v > mv || (v == mv && i < mi)) { mv = v; mi = i; }
        }
        f_rec[row] = mi;
    }
    if (t < B_) {
        float mv = -2.0f; int mi = 0;
        for (int s = 0; s < SPLITS_B; s++) {
            float v = g_bval[t * SPLITS_B + s];
            int   i = g_bidx[t * SPLITS_B + s];
            if (v > mv || (v == mv && i < mi)) { mv = v; mi = i; }
        }
        f_bon[t] = mi;
    }
    __syncthreads();

    if (t < B_) {
        const int b = t;
        int acc = 0, emitted = 0;
        bool chain = true;
        for (int n = 0; n < N_; n++) {
            int idx = b * N_ + n;
            int tok = ids[idx];
            float p = verify[((long)b * 9 + n) * V_ + tok];
            float q = draft[(long)idx * V_ + tok];
            float u = f_su[idx];
            bool a = __fmul_rn(u, q) < p;
            acc += a ? 1 : 0;
            if (chain) { if (a) emitted++; else chain = false; }
        }
        int final_tok = (emitted < N_) ? f_rec[b * N_ + emitted] : f_bon[b];
        for (int i = 0; i <= N_; i++) {
            float val;
            if (i < emitted)       val = (float)ids[b * N_ + i];
            else if (i == emitted) val = (float)final_tok;
            else                   val = -1.0f;
            out[b * (N_ + 1) + i] = val;
        }
        out[B_ * (N_ + 1) + b]       = (float)acc;      // accepted_token_num
        out[B_ * (N_ + 1) + B_ + b]  = (float)emitted;  // emitted_token_num
    }

    // reset for next graph replay
    if (t == 0) g_done = 0;
}

// ---------------- host launch ----------------
extern "C" void kernel_launch(void* const* d_in, const int* in_sizes, int n_in,
                              void* d_out, int out_size)
{
    // Bind inputs BY ELEMENT COUNT:
    const int*   draft_ids = nullptr;
    const float* draft_p   = nullptr;
    const float* verify_p  = nullptr;
    for (int i = 0; i < n_in; i++) {
        long sz = in_sizes[i];
        if (sz == (long)ROWS)                 draft_ids = (const int*)d_in[i];
        else if (sz == (long)B_ * N_ * V_)    draft_p   = (const float*)d_in[i];
        else if (sz == (long)B_ * 9 * V_)     verify_p  = (const float*)d_in[i];
    }
    float* out = (float*)d_out;

    // key(1) = (0, 1); split(key, 3) fold-like (partitionable)
    uint32_t ku0, ku1, kr0, kr1, kb0, kb1;
    threefry2x32_host(0u, 1u, 0u, 0u, &ku0, &ku1);
    threefry2x32_host(0u, 1u, 0u, 1u, &kr0, &kr1);
    threefry2x32_host(0u, 1u, 0u, 2u, &kb0, &kb1);

    fused_kernel<<<GRID_TOT, THREADS_R>>>(
        verify_p, draft_p, draft_ids, out, ku0, ku1, kr0, kr1, kb0, kb1, 1u);
}

// round 12
// speedup vs baseline: 1.3636x; 1.3636x over previous
#include <cuda_runtime.h>
#include <cstdint>

// ---------------------------------------------------------------------------
// RejectionSampler: chain speculative sampling, flashinfer-style.
// JAX threefry2x32 PARTITIONABLE streams (bit-exact, verified rel_err=0.0):
//   split(key,3):  key_i = threefry2x32(key, 0, i)
//   random_bits32: bits_j = o0 ^ o1 of threefry2x32(key, 0, j)
// argmax(log(x+EPS)+gumbel) computed as argmax x / (-log2 u)  (monotone).
// R12: revert to R8's proven funnelshift threefry (mul.wide path was 35%
//      slower in practice, R10/R11). Keep division-free compare + lg2
//      domain. Bonus blocks FIRST + SPLITS_B=32 to kill the long-block
//      straggler tail.
// Output FLOAT32: [ (B,N+1) tokens | (B,) accepted | (B,) emitted ]
// ---------------------------------------------------------------------------

#define B_  64
#define N_  8
#define V_  128000
#define ROWS (B_ * N_)              // 512
#define SPLITS_R 25
#define SPLITS_B 32
#define THREADS_R 256
#define WARPS_R (THREADS_R / 32)    // 8
#define CHUNK_R (V_ / SPLITS_R)     // 5120 elements per block
#define WCHUNK4 ((CHUNK_R / WARPS_R) / 4) // 160 float4 per warp
#define WITERS  (WCHUNK4 / 32)      // 5 exact iterations
#define GRID_REC (ROWS * SPLITS_R)  // 12800
#define GRID_BON (B_ * SPLITS_B)    // 2048
#define GRID_TOT (GRID_REC + GRID_BON)
#define CAP 128                     // per-warp per-iteration buffer
#define TINY_F 1.17549435e-38f

// scratch (no allocations allowed)
__device__ float g_rval[ROWS * SPLITS_R];
__device__ int   g_ridx[ROWS * SPLITS_R];
__device__ float g_bval[B_ * SPLITS_B];
__device__ int   g_bidx[B_ * SPLITS_B];
__device__ unsigned g_done = 0;

// ---------------- threefry2x32 (JAX-compatible, funnelshift rotates) -------
__host__ __device__ __forceinline__ void threefry2x32(
    uint32_t k0, uint32_t k1, uint32_t x0, uint32_t x1,
    uint32_t* y0, uint32_t* y1)
{
    uint32_t k2 = k0 ^ k1 ^ 0x1BD11BDAu;
    x0 += k0; x1 += k1;
#ifdef __CUDA_ARCH__
#define ROTL32(v, r) __funnelshift_l((v), (v), (r))
#else
#define ROTL32(v, r) (((v) << (r)) | ((v) >> (32 - (r))))
#endif
#define TF_RND(r) { x0 += x1; x1 = ROTL32(x1, r); x1 ^= x0; }
    TF_RND(13) TF_RND(15) TF_RND(26) TF_RND(6)   x0 += k1; x1 += k2 + 1u;
    TF_RND(17) TF_RND(29) TF_RND(16) TF_RND(24)  x0 += k2; x1 += k0 + 2u;
    TF_RND(13) TF_RND(15) TF_RND(26) TF_RND(6)   x0 += k0; x1 += k1 + 3u;
    TF_RND(17) TF_RND(29) TF_RND(16) TF_RND(24)  x0 += k1; x1 += k2 + 4u;
    TF_RND(13) TF_RND(15) TF_RND(26) TF_RND(6)   x0 += k2; x1 += k0 + 5u;
#undef TF_RND
#undef ROTL32
    *y0 = x0; *y1 = x1;
}

// partitionable 32-bit draw: counter (0, j), output o0 ^ o1
__device__ __forceinline__ uint32_t tf_bits32(uint32_t k0, uint32_t k1, uint32_t j) {
    uint32_t o0, o1;
    threefry2x32(k0, k1, 0u, j, &o0, &o1);
    return o0 ^ o1;
}

// bits -> uniform [0,1) exactly as JAX
__device__ __forceinline__ float bits_to_u(uint32_t bits) {
    return __uint_as_float((bits >> 9) | 0x3f800000u) - 1.0f;
}
// bits -> L = -log2(u') with u' = (u==0 ? tiny : u)   (gumbel path, lg2 domain;
// the ln2 scale cancels in argmax and is applied consistently everywhere)
__device__ __forceinline__ float bits_to_L(uint32_t bits) {
    float u = bits_to_u(bits);
    if (u == 0.0f) u = TINY_F;
    return -__log2f(u);
}

// warp-wide argmax butterfly (max value, min index on tie)
__device__ __forceinline__ void warp_argmax(float& bv, int& bi) {
#pragma unroll
    for (int o = 16; o > 0; o >>= 1) {
        float v2 = __shfl_xor_sync(0xFFFFFFFFu, bv, o);
        int   i2 = __shfl_xor_sync(0xFFFFFFFFu, bi, o);
        if (v2 > bv || (v2 == bv && i2 < bi)) { bv = v2; bi = i2; }
    }
}

// ---------------- fused kernel ----------------
// blocks [0, GRID_BON): bonus argmax (long RNG-dense work starts first)
// blocks [GRID_BON, GRID_TOT): recovered residual argmax with compaction
__global__ __launch_bounds__(THREADS_R)
void fused_kernel(const float* __restrict__ verify,
                  const float* __restrict__ draft,
                  const int* __restrict__ ids,
                  float* __restrict__ out,
                  uint32_t ku0, uint32_t ku1,
                  uint32_t kr0, uint32_t kr1,
                  uint32_t kb0, uint32_t kb1)
{
    __shared__ uint2 ebuf[WARPS_R][CAP];    // packed (value bits, index)
    __shared__ float swv[WARPS_R];
    __shared__ int   swi[WARPS_R];
    __shared__ float f_su[ROWS];
    __shared__ int   f_rec[ROWS];
    __shared__ int   f_bon[B_];
    __shared__ unsigned s_rank;

    const int t    = threadIdx.x;
    const int lane = t & 31;
    const int warp = t >> 5;

    float bv = -1.0f;
    int   bi = 0;

    if (blockIdx.x >= GRID_BON) {
        // ---- recovered: compaction, drain each iteration ----
        const int rbid = blockIdx.x - GRID_BON;
        const int row = rbid / SPLITS_R;            // 0..511
        const int s   = rbid % SPLITS_R;
        const long vOff = ((long)(row >> 3) * 9 + (row & 7)) * V_;
        const long dOff = (long)row * V_;
        const int v0 = s * CHUNK_R;

        const float4* vr4 = (const float4*)(verify + vOff + v0);
        const float4* dr4 = (const float4*)(draft  + dOff + v0);

        const int qbase = warp * WCHUNK4;
        const uint32_t rowbase = (uint32_t)row * (uint32_t)V_;
        bi = v0;

#pragma unroll
        for (int it = 0; it < WITERS; it++) {
            int q = qbase + it * 32 + lane;         // always in range
            float4 va = vr4[q], da = dr4[q];
            float r[4] = { va.x - da.x, va.y - da.y, va.z - da.z, va.w - da.w };
            int ebase = v0 + q * 4;
            int cnt = 0;                             // warp-uniform
#pragma unroll
            for (int j = 0; j < 4; j++) {
                bool pos = r[j] > 0.0f;
                unsigned m = __ballot_sync(0xFFFFFFFFu, pos);
                if (pos) {
                    int slot = cnt + __popc(m & ((1u << lane) - 1u));
                    ebuf[warp][slot] = make_uint2(__float_as_uint(r[j]),
                                                  (uint32_t)(ebase + j));
                }
                cnt += __popc(m);
            }
            __syncwarp();
            // drain: threefry only for compacted positives; division-free test
            for (int k = lane; k < cnt; k += 32) {
                uint2 e = ebuf[warp][k];
                float r_ = __uint_as_float(e.x);
                uint32_t bits = tf_bits32(kr0, kr1, rowbase + e.y);
                float L = bits_to_L(bits);
                if (r_ > bv * L) {                   // r/L > bv  (all positive)
                    bv = __fdividef(r_, L);
                    bi = (int)e.y;
                }
            }
            __syncwarp();
        }

        warp_argmax(bv, bi);
        if (lane == 0) { swv[warp] = bv; swi[warp] = bi; }
        __syncthreads();
        if (warp == 0) {
            float v = (lane < WARPS_R) ? swv[lane] : -2.0f;
            int   i = (lane < WARPS_R) ? swi[lane] : 0x7FFFFFFF;
            warp_argmax(v, i);
            if (lane == 0) {
                g_rval[row * SPLITS_R + s] = v;
                g_ridx[row * SPLITS_R + s] = i;
            }
        }
    } else {
        // ---- bonus: all elements need RNG ----
        const int bid = blockIdx.x;
        const int b = bid / SPLITS_B;               // 0..63
        const int s = bid % SPLITS_B;
        const long vOff = ((long)b * 9 + 8) * V_;

        const int chunk = V_ / SPLITS_B;            // 4000
        const int v0 = s * chunk;
        const float4* p4 = (const float4*)(verify + vOff + v0);
        bi = v0;

        const int n4 = chunk / 4;                   // 1000
        for (int q = t; q < n4; q += THREADS_R) {
            float4 pa = p4[q];
            int vbase = v0 + q * 4;
            uint32_t cbase = (uint32_t)b * (uint32_t)V_ + (uint32_t)vbase;
            float f[4] = { pa.x, pa.y, pa.z, pa.w };
#pragma unroll
            for (int j = 0; j < 4; j++) {
                uint32_t bits = tf_bits32(kb0, kb1, cbase + j);
                float L = bits_to_L(bits);
                if (f[j] > bv * L) {                 // f/L > bv (f>0 softmax)
                    bv = __fdividef(f[j], L);
                    bi = vbase + j;
                }
            }
        }

        warp_argmax(bv, bi);
        if (lane == 0) { swv[warp] = bv; swi[warp] = bi; }
        __syncthreads();
        if (warp == 0) {
            float v = (lane < WARPS_R) ? swv[lane] : -2.0f;
            int   i = (lane < WARPS_R) ? swi[lane] : 0x7FFFFFFF;
            warp_argmax(v, i);
            if (lane == 0) {
                g_bval[b * SPLITS_B + s] = v;
                g_bidx[b * SPLITS_B + s] = i;
            }
        }
    }

    // ---- last-block finalize ----
    __threadfence();
    if (t == 0) s_rank = atomicAdd(&g_done, 1u);
    __syncthreads();
    if (s_rank != GRID_TOT - 1) return;

    for (int i = t; i < ROWS; i += THREADS_R)
        f_su[i] = bits_to_u(tf_bits32(ku0, ku1, (uint32_t)i));

    for (int row = t; row < ROWS; row += THREADS_R) {
        float mv = -2.0f; int mi = 0;
        for (int s = 0; s < SPLITS_R; s++) {
            float v = g_rval[row * SPLITS_R + s];
            int   i = g_ridx[row * SPLITS_R + s];
            if (v > mv || (v == mv && i < mi)) { mv = v; mi = i; }
        }
        f_rec[row] = mi;
    }
    if (t < B_) {
        float mv = -2.0f; int mi = 0;
        for (int s = 0; s < SPLITS_B; s++) {
            float v = g_bval[t * SPLITS_B + s];
            int   i = g_bidx[t * SPLITS_B + s];
            if (v > mv || (v == mv && i < mi)) { mv = v; mi = i; }
        }
        f_bon[t] = mi;
    }
    __syncthreads();

    if (t < B_) {
        const int b = t;
        int acc = 0, emitted = 0;
        bool chain = true;
        for (int n = 0; n < N_; n++) {
            int idx = b * N_ + n;
            int tok = ids[idx];
            float p = verify[((long)b * 9 + n) * V_ + tok];
            float q = draft[(long)idx * V_ + tok];
            float u = f_su[idx];
            bool a = __fmul_rn(u, q) < p;
            acc += a ? 1 : 0;
            if (chain) { if (a) emitted++; else chain = false; }
        }
        int final_tok = (emitted < N_) ? f_rec[b * N_ + emitted] : f_bon[b];
        for (int i = 0; i <= N_; i++) {
            float val;
            if (i < emitted)       val = (float)ids[b * N_ + i];
            else if (i == emitted) val = (float)final_tok;
            else                   val = -1.0f;
            out[b * (N_ + 1) + i] = val;
        }
        out[B_ * (N_ + 1) + b]       = (float)acc;      // accepted_token_num
        out[B_ * (N_ + 1) + B_ + b]  = (float)emitted;  // emitted_token_num
    }

    // reset for next graph replay
    if (t == 0) g_done = 0;
}

// ---------------- host launch ----------------
extern "C" void kernel_launch(void* const* d_in, const int* in_sizes, int n_in,
                              void* d_out, int out_size)
{
    // Bind inputs BY ELEMENT COUNT:
    const int*   draft_ids = nullptr;
    const float* draft_p   = nullptr;
    const float* verify_p  = nullptr;
    for (int i = 0; i < n_in; i++) {
        long sz = in_sizes[i];
        if (sz == (long)ROWS)                 draft_ids = (const int*)d_in[i];
        else if (sz == (long)B_ * N_ * V_)    draft_p   = (const float*)d_in[i];
        else if (sz == (long)B_ * 9 * V_)     verify_p  = (const float*)d_in[i];
    }
    float* out = (float*)d_out;

    // key(1) = (0, 1); split(key, 3) fold-like (partitionable)
    uint32_t ku0, ku1, kr0, kr1, kb0, kb1;
    threefry2x32(0u, 1u, 0u, 0u, &ku0, &ku1);
    threefry2x32(0u, 1u, 0u, 1u, &kr0, &kr1);
    threefry2x32(0u, 1u, 0u, 2u, &kb0, &kb1);

    fused_kernel<<<GRID_TOT, THREADS_R>>>(
        verify_p, draft_p, draft_ids, out, ku0, ku1, kr0, kr1, kb0, kb1);
}

// round 15
// speedup vs baseline: 1.3917x; 1.0206x over previous
#include <cuda_runtime.h>
#include <cstdint>

// ---------------------------------------------------------------------------
// RejectionSampler: chain speculative sampling, flashinfer-style.
// JAX threefry2x32 PARTITIONABLE streams (bit-exact, verified rel_err=0.0):
//   split(key,3):  key_i = threefry2x32(key, 0, i)
//   random_bits32: bits_j = o0 ^ o1 of threefry2x32(key, 0, j)
// argmax(log(x+EPS)+gumbel) computed as argmax x / (-log u)  (monotone).
// R13: exact R8 structure (best: 193.6us) + threefry ADDs emitted as
//      mad.lo.u32 with a runtime-opaque multiplier ("one"=1) -> IMAD on the
//      idle fma pipe. Rotates stay funnelshift (R10/R11 proved mul.wide
//      rotates are a loss). alu/call 57->41, fma/call 16->48.
// Output FLOAT32: [ (B,N+1) tokens | (B,) accepted | (B,) emitted ]
// ---------------------------------------------------------------------------

#define B_  64
#define N_  8
#define V_  128000
#define ROWS (B_ * N_)              // 512
#define SPLITS_R 25
#define SPLITS_B 16
#define THREADS_R 256
#define WARPS_R (THREADS_R / 32)    // 8
#define CHUNK_R (V_ / SPLITS_R)     // 5120 elements per block
#define WCHUNK4 ((CHUNK_R / WARPS_R) / 4) // 160 float4 per warp
#define WITERS  (WCHUNK4 / 32)      // 5 exact iterations
#define GRID_REC (ROWS * SPLITS_R)  // 12800
#define GRID_BON (B_ * SPLITS_B)    // 1024
#define GRID_TOT (GRID_REC + GRID_BON)
#define CAP 128                     // per-warp per-iteration buffer
#define TINY_F 1.17549435e-38f

// scratch (no allocations allowed)
__device__ float g_rval[ROWS * SPLITS_R];
__device__ int   g_ridx[ROWS * SPLITS_R];
__device__ float g_bval[B_ * SPLITS_B];
__device__ int   g_bidx[B_ * SPLITS_B];
__device__ unsigned g_done = 0;

// opaque add: a + b as IMAD(a, one, b) on the fma pipe; 'one'=1 is a runtime
// kernel argument so ptxas cannot canonicalize back to IADD3.
__device__ __forceinline__ uint32_t madd(uint32_t a, uint32_t one, uint32_t b) {
    uint32_t d;
    asm("mad.lo.u32 %0, %1, %2, %3;" : "=r"(d) : "r"(a), "r"(one), "r"(b));
    return d;
}

// ---------------- threefry2x32 (JAX-compatible) ----------------
// Device version: funnelshift rotates (alu), opaque-mad adds (fma pipe).
__device__ __forceinline__ void threefry2x32_dev(
    uint32_t k0, uint32_t k1, uint32_t x0, uint32_t x1,
    uint32_t one, uint32_t* y0, uint32_t* y1)
{
    uint32_t k2 = k0 ^ k1 ^ 0x1BD11BDAu;
    // key-schedule constants (uniform, hoisted by ptxas)
    uint32_t kc1 = k2 + 1u, kc2 = k0 + 2u, kc3 = k1 + 3u,
             kc4 = k2 + 4u, kc5 = k0 + 5u;
    x0 = madd(x0, one, k0); x1 = madd(x1, one, k1);
#define TF_RND(r) { x0 = madd(x0, one, x1); \
    x1 = __funnelshift_l(x1, x1, (r)) ^ x0; }
    TF_RND(13) TF_RND(15) TF_RND(26) TF_RND(6)
    x0 = madd(x0, one, k1); x1 = madd(x1, one, kc1);
    TF_RND(17) TF_RND(29) TF_RND(16) TF_RND(24)
    x0 = madd(x0, one, k2); x1 = madd(x1, one, kc2);
    TF_RND(13) TF_RND(15) TF_RND(26) TF_RND(6)
    x0 = madd(x0, one, k0); x1 = madd(x1, one, kc3);
    TF_RND(17) TF_RND(29) TF_RND(16) TF_RND(24)
    x0 = madd(x0, one, k1); x1 = madd(x1, one, kc4);
    TF_RND(13) TF_RND(15) TF_RND(26) TF_RND(6)
    x0 = madd(x0, one, k2); x1 = madd(x1, one, kc5);
#undef TF_RND
    *y0 = x0; *y1 = x1;
}

// host copy (plain shifts)
inline void threefry2x32_host(
    uint32_t k0, uint32_t k1, uint32_t x0, uint32_t x1,
    uint32_t* y0, uint32_t* y1)
{
    uint32_t k2 = k0 ^ k1 ^ 0x1BD11BDAu;
    x0 += k0; x1 += k1;
#define ROTL32(v, r) (((v) << (r)) | ((v) >> (32 - (r))))
#define TF_RND(r) { x0 += x1; x1 = ROTL32(x1, r); x1 ^= x0; }
    TF_RND(13) TF_RND(15) TF_RND(26) TF_RND(6)   x0 += k1; x1 += k2 + 1u;
    TF_RND(17) TF_RND(29) TF_RND(16) TF_RND(24)  x0 += k2; x1 += k0 + 2u;
    TF_RND(13) TF_RND(15) TF_RND(26) TF_RND(6)   x0 += k0; x1 += k1 + 3u;
    TF_RND(17) TF_RND(29) TF_RND(16) TF_RND(24)  x0 += k1; x1 += k2 + 4u;
    TF_RND(13) TF_RND(15) TF_RND(26) TF_RND(6)   x0 += k2; x1 += k0 + 5u;
#undef TF_RND
#undef ROTL32
    *y0 = x0; *y1 = x1;
}

// partitionable 32-bit draw: counter (0, j), output o0 ^ o1
__device__ __forceinline__ uint32_t tf_bits32(uint32_t k0, uint32_t k1,
                                              uint32_t j, uint32_t one) {
    uint32_t o0, o1;
    threefry2x32_dev(k0, k1, 0u, j, one, &o0, &o1);
    return o0 ^ o1;
}

// bits -> uniform [0,1) exactly as JAX
__device__ __forceinline__ float bits_to_u(uint32_t bits) {
    return __uint_as_float((bits >> 9) | 0x3f800000u) - 1.0f;
}
// bits -> E = -log(u') with u' = (u==0 ? tiny : u)   (gumbel path)
__device__ __forceinline__ float bits_to_E(uint32_t bits) {
    float u = bits_to_u(bits);
    if (u == 0.0f) u = TINY_F;
    return -__logf(u);
}

// warp-wide argmax butterfly (max value, min index on tie)
__device__ __forceinline__ void warp_argmax(float& bv, int& bi) {
#pragma unroll
    for (int o = 16; o > 0; o >>= 1) {
        float v2 = __shfl_xor_sync(0xFFFFFFFFu, bv, o);
        int   i2 = __shfl_xor_sync(0xFFFFFFFFu, bi, o);
        if (v2 > bv || (v2 == bv && i2 < bi)) { bv = v2; bi = i2; }
    }
}

// ---------------- fused kernel ----------------
// blocks [0, GRID_REC): recovered residual argmax with warp compaction
// blocks [GRID_REC, GRID_TOT): bonus argmax (all elements need RNG)
__global__ __launch_bounds__(THREADS_R, 8)
void fused_kernel(const float* __restrict__ verify,
                  const float* __restrict__ draft,
                  const int* __restrict__ ids,
                  float* __restrict__ out,
                  uint32_t ku0, uint32_t ku1,
                  uint32_t kr0, uint32_t kr1,
                  uint32_t kb0, uint32_t kb1,
                  uint32_t one)
{
    __shared__ uint2 ebuf[WARPS_R][CAP];    // packed (value bits, index)
    __shared__ float swv[WARPS_R];
    __shared__ int   swi[WARPS_R];
    __shared__ float f_su[ROWS];
    __shared__ int   f_rec[ROWS];
    __shared__ int   f_bon[B_];
    __shared__ unsigned s_rank;

    const int t    = threadIdx.x;
    const int lane = t & 31;
    const int warp = t >> 5;

    float bv = -1.0f;
    int   bi = 0;

    if (blockIdx.x < GRID_REC) {
        // ---- recovered: compaction, drain each iteration ----
        const int row = blockIdx.x / SPLITS_R;      // 0..511
        const int s   = blockIdx.x % SPLITS_R;
        const long vOff = ((long)(row >> 3) * 9 + (row & 7)) * V_;
        const long dOff = (long)row * V_;
        const int v0 = s * CHUNK_R;

        const float4* vr4 = (const float4*)(verify + vOff + v0);
        const float4* dr4 = (const float4*)(draft  + dOff + v0);

        const int qbase = warp * WCHUNK4;
        const uint32_t rowbase = (uint32_t)row * (uint32_t)V_;
        bi = v0;

#pragma unroll
        for (int it = 0; it < WITERS; it++) {
            int q = qbase + it * 32 + lane;         // always in range
            float4 va = vr4[q], da = dr4[q];
            float r[4] = { va.x - da.x, va.y - da.y, va.z - da.z, va.w - da.w };
            int ebase = v0 + q * 4;
            int cnt = 0;                             // warp-uniform
#pragma unroll
            for (int j = 0; j < 4; j++) {
                bool pos = r[j] > 0.0f;
                unsigned m = __ballot_sync(0xFFFFFFFFu, pos);
                if (pos) {
                    int slot = cnt + __popc(m & ((1u << lane) - 1u));
                    ebuf[warp][slot] = make_uint2(__float_as_uint(r[j]),
                                                  (uint32_t)(ebase + j));
                }
                cnt += __popc(m);
            }
            __syncwarp();
            // drain: threefry only for compacted positives
            for (int k = lane; k < cnt; k += 32) {
                uint2 e = ebuf[warp][k];
                float r_  = __uint_as_float(e.x);
                int   ix  = (int)e.y;
                uint32_t bits = tf_bits32(kr0, kr1, rowbase + e.y, one);
                float f = __fdividef(r_, bits_to_E(bits));
                if (f > bv) { bv = f; bi = ix; }
            }
            __syncwarp();
        }

        warp_argmax(bv, bi);
        if (lane == 0) { swv[warp] = bv; swi[warp] = bi; }
        __syncthreads();
        if (warp == 0) {
            float v = (lane < WARPS_R) ? swv[lane] : -2.0f;
            int   i = (lane < WARPS_R) ? swi[lane] : 0x7FFFFFFF;
            warp_argmax(v, i);
            if (lane == 0) {
                g_rval[row * SPLITS_R + s] = v;
                g_ridx[row * SPLITS_R + s] = i;
            }
        }
    } else {
        // ---- bonus: all elements need RNG ----
        const int bid = blockIdx.x - GRID_REC;
        const int b = bid / SPLITS_B;               // 0..63
        const int s = bid % SPLITS_B;
        const long vOff = ((long)b * 9 + 8) * V_;

        const int chunk = V_ / SPLITS_B;            // 8000
        const int v0 = s * chunk;
        const float4* p4 = (const float4*)(verify + vOff + v0);
        bi = v0;

        const int n4 = chunk / 4;                   // 2000
        for (int q = t; q < n4; q += THREADS_R) {
            float4 pa = p4[q];
            int vbase = v0 + q * 4;
            uint32_t cbase = (uint32_t)b * (uint32_t)V_ + (uint32_t)vbase;
            float f[4] = { pa.x, pa.y, pa.z, pa.w };
#pragma unroll
            for (int j = 0; j < 4; j++) {
                uint32_t bits = tf_bits32(kb0, kb1, cbase + j, one);
                float sc = __fdividef(f[j], bits_to_E(bits));
                if (sc > bv) { bv = sc; bi = vbase + j; }
            }
        }

        warp_argmax(bv, bi);
        if (lane == 0) { swv[warp] = bv; swi[warp] = bi; }
        __syncthreads();
        if (warp == 0) {
            float v = (lane < WARPS_R) ? swv[lane] : -2.0f;
            int   i = (lane < WARPS_R) ? swi[lane] : 0x7FFFFFFF;
            warp_argmax(v, i);
            if (lane == 0) {
                g_bval[b * SPLITS_B + s] = v;
                g_bidx[b * SPLITS_B + s] = i;
            }
        }
    }

    // ---- last-block finalize ----
    __threadfence();
    if (t == 0) s_rank = atomicAdd(&g_done, 1u);
    __syncthreads();
    if (s_rank != GRID_TOT - 1) return;

    for (int i = t; i < ROWS; i += THREADS_R)
        f_su[i] = bits_to_u(tf_bits32(ku0, ku1, (uint32_t)i, one));

    for (int row = t; row < ROWS; row += THREADS_R) {
        float mv = -2.0f; int mi = 0;
        for (int s = 0; s < SPLITS_R; s++) {
            float v = g_rval[row * SPLITS_R + s];
            int   i = g_ridx[row * SPLITS_R + s];
            if (v > mv || (v == mv && i < mi)) { mv = v; mi = i; }
        }
        f_rec[row] = mi;
    }
    if (t < B_) {
        float mv = -2.0f; int mi = 0;
        for (int s = 0; s < SPLITS_B; s++) {
            float v = g_bval[t * SPLITS_B + s];
            int   i = g_bidx[t * SPLITS_B + s];
            if (v > mv || (v == mv && i < mi)) { mv = v; mi = i; }
        }
        f_bon[t] = mi;
    }
    __syncthreads();

    if (t < B_) {
        const int b = t;
        int acc = 0, emitted = 0;
        bool chain = true;
        for (int n = 0; n < N_; n++) {
            int idx = b * N_ + n;
            int tok = ids[idx];
            float p = verify[((long)b * 9 + n) * V_ + tok];
            float q = draft[(long)idx * V_ + tok];
            float u = f_su[idx];
            bool a = __fmul_rn(u, q) < p;
            acc += a ? 1 : 0;
            if (chain) { if (a) emitted++; else chain = false; }
        }
        int final_tok = (emitted < N_) ? f_rec[b * N_ + emitted] : f_bon[b];
        for (int i = 0; i <= N_; i++) {
            float val;
            if (i < emitted)       val = (float)ids[b * N_ + i];
            else if (i == emitted) val = (float)final_tok;
            else                   val = -1.0f;
            out[b * (N_ + 1) + i] = val;
        }
        out[B_ * (N_ + 1) + b]       = (float)acc;      // accepted_token_num
        out[B_ * (N_ + 1) + B_ + b]  = (float)emitted;  // emitted_token_num
    }

    // reset for next graph replay
    if (t == 0) g_done = 0;
}

// ---------------- host launch ----------------
extern "C" void kernel_launch(void* const* d_in, const int* in_sizes, int n_in,
                              void* d_out, int out_size)
{
    // Bind inputs BY ELEMENT COUNT:
    const int*   draft_ids = nullptr;
    const float* draft_p   = nullptr;
    const float* verify_p  = nullptr;
    for (int i = 0; i < n_in; i++) {
        long sz = in_sizes[i];
        if (sz == (long)ROWS)                 draft_ids = (const int*)d_in[i];
        else if (sz == (long)B_ * N_ * V_)    draft_p   = (const float*)d_in[i];
        else if (sz == (long)B_ * 9 * V_)     verify_p  = (const float*)d_in[i];
    }
    float* out = (float*)d_out;

    // key(1) = (0, 1); split(key, 3) fold-like (partitionable)
    uint32_t ku0, ku1, kr0, kr1, kb0, kb1;
    threefry2x32_host(0u, 1u, 0u, 0u, &ku0, &ku1);
    threefry2x32_host(0u, 1u, 0u, 1u, &kr0, &kr1);
    threefry2x32_host(0u, 1u, 0u, 2u, &kb0, &kb1);

    fused_kernel<<<GRID_TOT, THREADS_R>>>(
        verify_p, draft_p, draft_ids, out, ku0, ku1, kr0, kr1, kb0, kb1, 1u);
}